// round 9
// baseline (speedup 1.0000x reference)
#include <cuda_runtime.h>

// Problem dims
#define B_   256
#define T_   32
#define IN_  2312
#define H_   1024
#define OUT_ 10
#define BH   (B_ * H_)

// LIF constants
#define DT_TAUMEM 0.05f
#define DT_TAUSYN 0.2f

#define KSPL 8                      // split-K factor for GEMM2
#define NBLK 128                    // persistent grid size (single wave, <=148)

// Device-global scratch / state
__device__ float g_inp1[(long)T_ * BH];
__device__ float g_v1[BH], g_i1[BH];
__device__ float g_v2[BH], g_i2[BH];
__device__ float g_s1[BH];
__device__ float g_part[(long)KSPL * BH];
__device__ float g_vo[B_ * OUT_], g_io[B_ * OUT_];
__device__ unsigned g_bar;

__device__ __forceinline__ void lif_update(float& v, float& cur, float inp, float& s) {
    float vd = v + DT_TAUMEM * (cur - v);
    float id = cur - DT_TAUSYN * cur;
    s = (vd - 1.0f) > 0.0f ? 1.0f : 0.0f;
    v = (1.0f - s) * vd;
    cur = id + inp;
}

// ---- packed f32x2 helpers (FFMA2 path) ------------------------------------
__device__ __forceinline__ unsigned long long dup2(float x) {
    unsigned long long r;
    asm("mov.b64 %0, {%1, %1};" : "=l"(r) : "f"(x));
    return r;
}
__device__ __forceinline__ unsigned long long pk2(float x, float y) {
    unsigned long long r;
    asm("mov.b64 %0, {%1, %2};" : "=l"(r) : "f"(x), "f"(y));
    return r;
}
__device__ __forceinline__ void fma2(unsigned long long& d,
                                     unsigned long long a, unsigned long long b) {
    asm("fma.rn.f32x2 %0, %1, %2, %0;" : "+l"(d) : "l"(a), "l"(b));
}
__device__ __forceinline__ float2 up2(unsigned long long v) {
    float2 f;
    asm("mov.b64 {%0, %1}, %2;" : "=f"(f.x), "=f"(f.y) : "l"(v));
    return f;
}

// ---- device-wide barrier (valid: grid is a guaranteed single wave) ---------
__device__ __forceinline__ void grid_sync(unsigned target) {
    __syncthreads();
    if (threadIdx.x == 0) {
        __threadfence();                       // release prior stores to L2
        atomicAdd(&g_bar, 1u);
        while (*(volatile unsigned*)&g_bar < target) { }
    }
    __syncthreads();
}

// ---------------------------------------------------------------------------
__global__ void init_kernel(float* __restrict__ out) {
    int idx = blockIdx.x * blockDim.x + threadIdx.x;
    if (idx == 0) g_bar = 0u;
    if (idx < BH) {
        g_v1[idx] = 0.f; g_i1[idx] = 0.f;
        g_v2[idx] = 0.f; g_i2[idx] = 0.f;
    }
    if (idx < B_ * OUT_) {
        g_vo[idx] = 0.f; g_io[idx] = 0.f;
        out[idx] = 0.f;
    }
}

// ---------------------------------------------------------------------------
// GEMM1: g_inp1[t][b][h] = x[m=b*32+t,:] . W1[h,:] + b1[h]
// M=8192, N=1024, K=2312. Tile 128x128, BK=8, 256 thr, 8x8/thread, FFMA2.
// (measured at ~95% of FFMA2 issue peak — unchanged)
// ---------------------------------------------------------------------------
#define G1_BK 8
#define G1_PAD 132
__global__ void __launch_bounds__(256) gemm1_kernel(
    const float* __restrict__ x, const float* __restrict__ W1,
    const float* __restrict__ b1)
{
    __shared__ float As[2][G1_BK][G1_PAD];
    __shared__ float Bs[2][G1_BK][G1_PAD];

    int tid = threadIdx.x;
    int m0 = blockIdx.y * 128;
    int n0 = blockIdx.x * 128;

    int lrow = tid >> 1;
    int lk4  = (tid & 1) * 4;
    const float* aptr = x  + (long)(m0 + lrow) * IN_ + lk4;
    const float* bptr = W1 + (long)(n0 + lrow) * IN_ + lk4;

    int tx = tid & 15;
    int ty = tid >> 4;

    unsigned long long acc[8][4];
#pragma unroll
    for (int r = 0; r < 8; r++)
#pragma unroll
        for (int c = 0; c < 4; c++) acc[r][c] = 0ULL;

    float4 ra = *(const float4*)aptr;
    float4 rb = *(const float4*)bptr;
#pragma unroll
    for (int i = 0; i < 4; i++) {
        As[0][lk4 + i][lrow] = ((const float*)&ra)[i];
        Bs[0][lk4 + i][lrow] = ((const float*)&rb)[i];
    }
    __syncthreads();

    const int nIter = IN_ / G1_BK;  // 289
    for (int it = 0; it < nIter; it++) {
        int cur = it & 1, nxt = cur ^ 1;
        if (it + 1 < nIter) {
            ra = *(const float4*)(aptr + (long)(it + 1) * G1_BK);
            rb = *(const float4*)(bptr + (long)(it + 1) * G1_BK);
        }
#pragma unroll
        for (int k = 0; k < G1_BK; k++) {
            float4 a0 = *(const float4*)&As[cur][k][ty * 4];
            float4 a1 = *(const float4*)&As[cur][k][ty * 4 + 64];
            float4 b0 = *(const float4*)&Bs[cur][k][tx * 4];
            float4 b1 = *(const float4*)&Bs[cur][k][tx * 4 + 64];
            unsigned long long ap[8], bp[4];
            ap[0] = dup2(a0.x); ap[1] = dup2(a0.y); ap[2] = dup2(a0.z); ap[3] = dup2(a0.w);
            ap[4] = dup2(a1.x); ap[5] = dup2(a1.y); ap[6] = dup2(a1.z); ap[7] = dup2(a1.w);
            bp[0] = pk2(b0.x, b0.y); bp[1] = pk2(b0.z, b0.w);
            bp[2] = pk2(b1.x, b1.y); bp[3] = pk2(b1.z, b1.w);
#pragma unroll
            for (int r = 0; r < 8; r++)
#pragma unroll
                for (int c = 0; c < 4; c++) fma2(acc[r][c], ap[r], bp[c]);
        }
        if (it + 1 < nIter) {
#pragma unroll
            for (int i = 0; i < 4; i++) {
                As[nxt][lk4 + i][lrow] = ((const float*)&ra)[i];
                Bs[nxt][lk4 + i][lrow] = ((const float*)&rb)[i];
            }
        }
        __syncthreads();
    }

#pragma unroll
    for (int r = 0; r < 8; r++) {
        int m = m0 + ty * 4 + (r & 3) + (r >> 2) * 64;
        int b = m >> 5;
        int t = m & 31;
        long orow = ((long)t * B_ + b) * H_;
#pragma unroll
        for (int c = 0; c < 4; c++) {
            int h = n0 + tx * 4 + (c & 1) * 2 + (c >> 1) * 64;
            float2 v = up2(acc[r][c]);
            g_inp1[orow + h]     = v.x + b1[h];
            g_inp1[orow + h + 1] = v.y + b1[h + 1];
        }
    }
}

// ---------------------------------------------------------------------------
// Persistent recurrence kernel: all T steps, 128 blocks x 512 threads.
// Per step: phase A = GEMM2 split-K partial (block -> (n-tile, m-tile, z)),
//           grid sync, phase B = reduce+LIF2 + out-GEMV+LIF-out + s1-LIF(t+1),
//           grid sync.
// Cross-block traffic (g_s1, g_part) via stcg/ldcg (L2-coherent).
// ---------------------------------------------------------------------------
__global__ void __launch_bounds__(512) persist_kernel(
    const float* __restrict__ W2, const float* __restrict__ Wout,
    const float* __restrict__ b2, const float* __restrict__ bout,
    float* __restrict__ out)
{
    __shared__ float As[2][G1_BK][G1_PAD];
    __shared__ float Bs[2][G1_BK][G1_PAD];
    __shared__ float s2s[2][H_];

    int tid = threadIdx.x;
    int bid = blockIdx.x;
    int wid = tid >> 5, lane = tid & 31;

    // phase-A geometry
    int n0 = (bid & 7) << 7;          // h tile
    int m0 = ((bid >> 3) & 1) << 7;   // batch tile
    int z  = bid >> 4;                // split-K chunk
    int kbase = z << 7;

    int half = (tid < 256);           // warps 0-7 load A (s1), warps 8-15 load B (W2)
    int ltid = tid & 255;
    int lrow = ltid >> 1;
    int lk4  = (ltid & 1) * 4;
    const float* gsrc = half ? (g_s1 + (long)(m0 + lrow) * H_ + kbase + lk4)
                             : (W2   + (long)(n0 + lrow) * H_ + kbase + lk4);
    float* sbase = half ? &As[0][0][0] : &Bs[0][0][0];

    int tx = tid & 15;                // n group (8 cols)
    int ty = tid >> 4;                // m group (4 rows), 0..31

    unsigned sync_target = 0;

    // ---- t=0 layer-1 LIF (s1(0)) ----
    {
        long e = ((long)bid * 512 + tid) * 4;
        float4 inp = *(const float4*)&g_inp1[e];
        float4 v = *(float4*)&g_v1[e];
        float4 c = *(float4*)&g_i1[e];
        float4 s;
        lif_update(v.x, c.x, inp.x, s.x);
        lif_update(v.y, c.y, inp.y, s.y);
        lif_update(v.z, c.z, inp.z, s.z);
        lif_update(v.w, c.w, inp.w, s.w);
        *(float4*)&g_v1[e] = v;
        *(float4*)&g_i1[e] = c;
        __stcg((float4*)&g_s1[e], s);
    }
    sync_target += NBLK;
    grid_sync(sync_target);

    for (int t = 0; t < T_; t++) {
        // =================== phase A: GEMM2 split-K partial ===============
        unsigned long long acc[4][4];
#pragma unroll
        for (int r = 0; r < 4; r++)
#pragma unroll
            for (int c = 0; c < 4; c++) acc[r][c] = 0ULL;

        {
            float4 r0;
            if (half) r0 = __ldcg((const float4*)gsrc);
            else      r0 = *(const float4*)gsrc;
#pragma unroll
            for (int i = 0; i < 4; i++)
                sbase[(lk4 + i) * G1_PAD + lrow] = ((const float*)&r0)[i];
        }
        __syncthreads();

        const int nIter = 16;   // 128-wide K chunk / BK=8
#pragma unroll 1
        for (int it = 0; it < nIter; it++) {
            int cur = it & 1, nxt = cur ^ 1;
            float4 rn;
            if (it + 1 < nIter) {
                if (half) rn = __ldcg((const float4*)(gsrc + (it + 1) * G1_BK));
                else      rn = *(const float4*)(gsrc + (it + 1) * G1_BK);
            }
#pragma unroll
            for (int k = 0; k < G1_BK; k++) {
                float4 a0 = *(const float4*)&As[cur][k][ty * 4];
                float4 b0 = *(const float4*)&Bs[cur][k][tx * 4];
                float4 b1 = *(const float4*)&Bs[cur][k][tx * 4 + 64];
                unsigned long long ap[4], bp[4];
                ap[0] = dup2(a0.x); ap[1] = dup2(a0.y); ap[2] = dup2(a0.z); ap[3] = dup2(a0.w);
                bp[0] = pk2(b0.x, b0.y); bp[1] = pk2(b0.z, b0.w);
                bp[2] = pk2(b1.x, b1.y); bp[3] = pk2(b1.z, b1.w);
#pragma unroll
                for (int r = 0; r < 4; r++)
#pragma unroll
                    for (int c = 0; c < 4; c++) fma2(acc[r][c], ap[r], bp[c]);
            }
            if (it + 1 < nIter) {
#pragma unroll
                for (int i = 0; i < 4; i++)
                    sbase[nxt * (G1_BK * G1_PAD) + (lk4 + i) * G1_PAD + lrow] =
                        ((const float*)&rn)[i];
                __syncthreads();
            }
        }

        {
            long zbase = (long)z * BH;
#pragma unroll
            for (int r = 0; r < 4; r++) {
                int b = m0 + ty * 4 + r;
                long row = zbase + (long)b * H_;
#pragma unroll
                for (int c = 0; c < 4; c++) {
                    int h = n0 + tx * 4 + (c >> 1) * 64 + (c & 1) * 2;
                    __stcg((float2*)&g_part[row + h], up2(acc[r][c]));
                }
            }
        }
        sync_target += NBLK;
        grid_sync(sync_target);

        // =================== phase B: tail =================================
        // reduce partials + LIF2 -> s2 (smem), 2 batches per block
#pragma unroll
        for (int rep = 0; rep < 2; rep++) {
            int b = bid * 2 + rep;
            int h = tid * 2;
            long idx = (long)b * H_ + h;
            float2 sum = *(const float2*)&b2[h];
#pragma unroll
            for (int zz = 0; zz < KSPL; zz++) {
                float2 p = __ldcg((const float2*)&g_part[(long)zz * BH + idx]);
                sum.x += p.x; sum.y += p.y;
            }
            float2 v = *(float2*)&g_v2[idx];
            float2 c = *(float2*)&g_i2[idx];
            float sx, sy;
            lif_update(v.x, c.x, sum.x, sx);
            lif_update(v.y, c.y, sum.y, sy);
            *(float2*)&g_v2[idx] = v;
            *(float2*)&g_i2[idx] = c;
            *(float2*)&s2s[rep][h] = make_float2(sx, sy);
        }
        __syncthreads();

        // output GEMV + LIF-out + rate accumulate (20 tasks over 16 warps)
        for (int task = wid; task < 2 * OUT_; task += 16) {
            int rep = task / OUT_;
            int o = task - rep * OUT_;
            float sum = 0.f;
#pragma unroll 8
            for (int j = lane; j < H_; j += 32)
                sum = fmaf(s2s[rep][j], __ldg(&Wout[o * H_ + j]), sum);
#pragma unroll
            for (int off = 16; off; off >>= 1)
                sum += __shfl_xor_sync(0xffffffff, sum, off);
            if (lane == 0) {
                int b = bid * 2 + rep;
                int idx = b * OUT_ + o;
                float v = g_vo[idx], cur = g_io[idx], s;
                lif_update(v, cur, sum + bout[o], s);
                g_vo[idx] = v; g_io[idx] = cur;
                out[idx] += s;
            }
        }

        // layer-1 LIF for step t+1
        if (t + 1 < T_) {
#pragma unroll
            for (int rep = 0; rep < 2; rep++) {
                int b = bid * 2 + rep;
                int h = tid * 2;
                long idx = (long)b * H_ + h;
                float2 inp = *(const float2*)&g_inp1[(long)(t + 1) * BH + idx];
                float2 v = *(float2*)&g_v1[idx];
                float2 c = *(float2*)&g_i1[idx];
                float sx, sy;
                lif_update(v.x, c.x, inp.x, sx);
                lif_update(v.y, c.y, inp.y, sy);
                *(float2*)&g_v1[idx] = v;
                *(float2*)&g_i1[idx] = c;
                __stcg((float2*)&g_s1[idx], make_float2(sx, sy));
            }
            sync_target += NBLK;
            grid_sync(sync_target);
        }
    }
}

// ---------------------------------------------------------------------------
extern "C" void kernel_launch(void* const* d_in, const int* in_sizes, int n_in,
                              void* d_out, int out_size)
{
    const float* x    = (const float*)d_in[0];
    const float* W1   = (const float*)d_in[1];
    const float* b1   = (const float*)d_in[2];
    const float* W2   = (const float*)d_in[3];
    const float* b2   = (const float*)d_in[4];
    const float* Wout = (const float*)d_in[5];
    const float* bout = (const float*)d_in[6];
    float* out = (float*)d_out;

    init_kernel<<<BH / 256, 256>>>(out);

    // Time-parallel input GEMM (FFMA2)
    gemm1_kernel<<<dim3(H_ / 128, (B_ * T_) / 128), 256>>>(x, W1, b1);

    // All T recurrence steps in one persistent kernel
    persist_kernel<<<NBLK, 512>>>(W2, Wout, b2, bout, out);
}

// round 10
// speedup vs baseline: 1.8373x; 1.8373x over previous
#include <cuda_runtime.h>

// Problem dims
#define B_   256
#define T_   32
#define IN_  2312
#define H_   1024
#define OUT_ 10
#define BH   (B_ * H_)

// LIF constants
#define DT_TAUMEM 0.05f
#define DT_TAUSYN 0.2f

// Device-global scratch
__device__ float g_inp1[(long)T_ * BH];   // x_t @ W1^T + b1, [t][b][h]
__device__ float g_w2t[(long)H_ * H_];    // W2 transposed: [k][h]

__device__ __forceinline__ void lif_update(float& v, float& cur, float inp, float& s) {
    float vd = v + DT_TAUMEM * (cur - v);
    float id = cur - DT_TAUSYN * cur;
    s = (vd - 1.0f) > 0.0f ? 1.0f : 0.0f;
    v = (1.0f - s) * vd;
    cur = id + inp;
}

// ---- packed f32x2 helpers (FFMA2 path, used by gemm1) ----------------------
__device__ __forceinline__ unsigned long long dup2(float x) {
    unsigned long long r;
    asm("mov.b64 %0, {%1, %1};" : "=l"(r) : "f"(x));
    return r;
}
__device__ __forceinline__ unsigned long long pk2(float x, float y) {
    unsigned long long r;
    asm("mov.b64 %0, {%1, %2};" : "=l"(r) : "f"(x), "f"(y));
    return r;
}
__device__ __forceinline__ void fma2(unsigned long long& d,
                                     unsigned long long a, unsigned long long b) {
    asm("fma.rn.f32x2 %0, %1, %2, %0;" : "+l"(d) : "l"(a), "l"(b));
}
__device__ __forceinline__ float2 up2(unsigned long long v) {
    float2 f;
    asm("mov.b64 {%0, %1}, %2;" : "=f"(f.x), "=f"(f.y) : "l"(v));
    return f;
}

// ---------------------------------------------------------------------------
// W2 transpose: g_w2t[k][h] = W2[h][k]
// ---------------------------------------------------------------------------
__global__ void transpose_kernel(const float* __restrict__ W2) {
    __shared__ float tile[32][33];
    int x = blockIdx.x * 32 + threadIdx.x;   // k
    int y0 = blockIdx.y * 32;                // h
#pragma unroll
    for (int i = threadIdx.y; i < 32; i += 8)
        tile[i][threadIdx.x] = W2[(long)(y0 + i) * H_ + x];
    __syncthreads();
    int xo = blockIdx.y * 32 + threadIdx.x;  // h
    int yo = blockIdx.x * 32;                // k
#pragma unroll
    for (int i = threadIdx.y; i < 32; i += 8)
        g_w2t[(long)(yo + i) * H_ + xo] = tile[threadIdx.x][i];
}

// ---------------------------------------------------------------------------
// GEMM1: g_inp1[t][b][h] = x[m=b*32+t,:] . W1[h,:] + b1[h]
// Tile 128x128, BK=8, 256 thr, 8x8/thread, FFMA2. (~95% FFMA2 peak)
// ---------------------------------------------------------------------------
#define G1_BK 8
#define G1_PAD 132
__global__ void __launch_bounds__(256) gemm1_kernel(
    const float* __restrict__ x, const float* __restrict__ W1,
    const float* __restrict__ b1)
{
    __shared__ float As[2][G1_BK][G1_PAD];
    __shared__ float Bs[2][G1_BK][G1_PAD];

    int tid = threadIdx.x;
    int m0 = blockIdx.y * 128;
    int n0 = blockIdx.x * 128;

    int lrow = tid >> 1;
    int lk4  = (tid & 1) * 4;
    const float* aptr = x  + (long)(m0 + lrow) * IN_ + lk4;
    const float* bptr = W1 + (long)(n0 + lrow) * IN_ + lk4;

    int tx = tid & 15;
    int ty = tid >> 4;

    unsigned long long acc[8][4];
#pragma unroll
    for (int r = 0; r < 8; r++)
#pragma unroll
        for (int c = 0; c < 4; c++) acc[r][c] = 0ULL;

    float4 ra = *(const float4*)aptr;
    float4 rb = *(const float4*)bptr;
#pragma unroll
    for (int i = 0; i < 4; i++) {
        As[0][lk4 + i][lrow] = ((const float*)&ra)[i];
        Bs[0][lk4 + i][lrow] = ((const float*)&rb)[i];
    }
    __syncthreads();

    const int nIter = IN_ / G1_BK;  // 289
    for (int it = 0; it < nIter; it++) {
        int cur = it & 1, nxt = cur ^ 1;
        if (it + 1 < nIter) {
            ra = *(const float4*)(aptr + (long)(it + 1) * G1_BK);
            rb = *(const float4*)(bptr + (long)(it + 1) * G1_BK);
        }
#pragma unroll
        for (int k = 0; k < G1_BK; k++) {
            float4 a0 = *(const float4*)&As[cur][k][ty * 4];
            float4 a1 = *(const float4*)&As[cur][k][ty * 4 + 64];
            float4 b0 = *(const float4*)&Bs[cur][k][tx * 4];
            float4 b1 = *(const float4*)&Bs[cur][k][tx * 4 + 64];
            unsigned long long ap[8], bp[4];
            ap[0] = dup2(a0.x); ap[1] = dup2(a0.y); ap[2] = dup2(a0.z); ap[3] = dup2(a0.w);
            ap[4] = dup2(a1.x); ap[5] = dup2(a1.y); ap[6] = dup2(a1.z); ap[7] = dup2(a1.w);
            bp[0] = pk2(b0.x, b0.y); bp[1] = pk2(b0.z, b0.w);
            bp[2] = pk2(b1.x, b1.y); bp[3] = pk2(b1.z, b1.w);
#pragma unroll
            for (int r = 0; r < 8; r++)
#pragma unroll
                for (int c = 0; c < 4; c++) fma2(acc[r][c], ap[r], bp[c]);
        }
        if (it + 1 < nIter) {
#pragma unroll
            for (int i = 0; i < 4; i++) {
                As[nxt][lk4 + i][lrow] = ((const float*)&ra)[i];
                Bs[nxt][lk4 + i][lrow] = ((const float*)&rb)[i];
            }
        }
        __syncthreads();
    }

#pragma unroll
    for (int r = 0; r < 8; r++) {
        int m = m0 + ty * 4 + (r & 3) + (r >> 2) * 64;
        int b = m >> 5;
        int t = m & 31;
        long orow = ((long)t * B_ + b) * H_;
#pragma unroll
        for (int c = 0; c < 4; c++) {
            int h = n0 + tx * 4 + (c & 1) * 2 + (c >> 1) * 64;
            float2 v = up2(acc[r][c]);
            g_inp1[orow + h]     = v.x + b1[h];
            g_inp1[orow + h + 1] = v.y + b1[h + 1];
        }
    }
}

// ---------------------------------------------------------------------------
// Persistent per-batch recurrence: block = one batch, 256 threads, all T steps.
// Thread owns h = 4*tid..4*tid+3. All LIF state in registers / smem.
// GEMM2 replaced by sparse accumulation of W2^T rows for active spikes
// (binary spikes: skipping zeros is fp-exact vs dense k-ordered sum).
// ---------------------------------------------------------------------------
__global__ void __launch_bounds__(256) batch_kernel(
    const float* __restrict__ Wout, const float* __restrict__ b2,
    const float* __restrict__ bout, float* __restrict__ out)
{
    __shared__ float s2s[H_];
    __shared__ int   acts[H_];
    __shared__ int   warp_cnt[8], warp_base[8], tot_s;
    __shared__ float vo_s[OUT_], io_s[OUT_], oacc[OUT_];

    int b = blockIdx.x;
    int tid = threadIdx.x;
    int wid = tid >> 5, lane = tid & 31;
    int h0 = tid * 4;

    if (tid < OUT_) { vo_s[tid] = 0.f; io_s[tid] = 0.f; oacc[tid] = 0.f; }

    float4 v1 = make_float4(0.f, 0.f, 0.f, 0.f), i1 = v1;
    float4 v2 = v1, i2 = v1;
    float4 b2r = *(const float4*)&b2[h0];
    const float4* W2T4 = (const float4*)g_w2t;
    const float* inp_base = g_inp1 + (long)b * H_ + h0;
    __syncthreads();

    for (int t = 0; t < T_; t++) {
        // ---- layer-1 LIF (dense, per-thread 4 neurons) ----
        float4 inp = __ldg((const float4*)(inp_base + (long)t * BH));
        float4 s;
        lif_update(v1.x, i1.x, inp.x, s.x);
        lif_update(v1.y, i1.y, inp.y, s.y);
        lif_update(v1.z, i1.z, inp.z, s.z);
        lif_update(v1.w, i1.w, inp.w, s.w);

        // ---- deterministic k-ordered compaction of active spikes ----
        int c0 = s.x > 0.5f, c1 = s.y > 0.5f, c2 = s.z > 0.5f, c3 = s.w > 0.5f;
        int cnt = c0 + c1 + c2 + c3;
        int incl = cnt;
#pragma unroll
        for (int off = 1; off < 32; off <<= 1) {
            int n = __shfl_up_sync(0xffffffff, incl, off);
            if (lane >= off) incl += n;
        }
        if (lane == 31) warp_cnt[wid] = incl;
        __syncthreads();
        if (tid == 0) {
            int run = 0;
#pragma unroll
            for (int w = 0; w < 8; w++) { warp_base[w] = run; run += warp_cnt[w]; }
            tot_s = run;
        }
        __syncthreads();
        int p = warp_base[wid] + incl - cnt;
        if (c0) acts[p++] = h0;
        if (c1) acts[p++] = h0 + 1;
        if (c2) acts[p++] = h0 + 2;
        if (c3) acts[p++] = h0 + 3;
        __syncthreads();
        int tot = tot_s;

        // ---- sparse GEMM2: acc = b2 + sum_{active k} W2T[k][h0..h0+3] ----
        float4 acc = b2r;
        int i = 0;
        for (; i + 4 <= tot; i += 4) {
            int k0 = acts[i], k1 = acts[i + 1], k2 = acts[i + 2], k3 = acts[i + 3];
            float4 w0 = __ldg(&W2T4[(long)k0 * 256 + tid]);
            float4 w1 = __ldg(&W2T4[(long)k1 * 256 + tid]);
            float4 w2 = __ldg(&W2T4[(long)k2 * 256 + tid]);
            float4 w3 = __ldg(&W2T4[(long)k3 * 256 + tid]);
            acc.x += w0.x; acc.y += w0.y; acc.z += w0.z; acc.w += w0.w;
            acc.x += w1.x; acc.y += w1.y; acc.z += w1.z; acc.w += w1.w;
            acc.x += w2.x; acc.y += w2.y; acc.z += w2.z; acc.w += w2.w;
            acc.x += w3.x; acc.y += w3.y; acc.z += w3.z; acc.w += w3.w;
        }
        for (; i < tot; i++) {
            float4 w0 = __ldg(&W2T4[(long)acts[i] * 256 + tid]);
            acc.x += w0.x; acc.y += w0.y; acc.z += w0.z; acc.w += w0.w;
        }

        // ---- layer-2 LIF -> s2 in smem ----
        float4 s2;
        lif_update(v2.x, i2.x, acc.x, s2.x);
        lif_update(v2.y, i2.y, acc.y, s2.y);
        lif_update(v2.z, i2.z, acc.z, s2.z);
        lif_update(v2.w, i2.w, acc.w, s2.w);
        *(float4*)&s2s[h0] = s2;
        __syncthreads();

        // ---- output GEMV + LIF-out + rate accumulate (10 tasks, 8 warps) ----
        for (int o = wid; o < OUT_; o += 8) {
            float sum = 0.f;
            const float* wrow = Wout + o * H_;
#pragma unroll 8
            for (int j = lane; j < H_; j += 32)
                sum = fmaf(s2s[j], __ldg(&wrow[j]), sum);
#pragma unroll
            for (int off = 16; off; off >>= 1)
                sum += __shfl_xor_sync(0xffffffff, sum, off);
            if (lane == 0) {
                float v = vo_s[o], cur = io_s[o], so;
                lif_update(v, cur, sum + bout[o], so);
                vo_s[o] = v; io_s[o] = cur;
                oacc[o] += so;
            }
        }
        __syncthreads();   // protect s2s/acts reuse next step
    }

    if (tid < OUT_) out[b * OUT_ + tid] = oacc[tid];
}

// ---------------------------------------------------------------------------
extern "C" void kernel_launch(void* const* d_in, const int* in_sizes, int n_in,
                              void* d_out, int out_size)
{
    const float* x    = (const float*)d_in[0];
    const float* W1   = (const float*)d_in[1];
    const float* b1   = (const float*)d_in[2];
    const float* W2   = (const float*)d_in[3];
    const float* b2   = (const float*)d_in[4];
    const float* Wout = (const float*)d_in[5];
    const float* bout = (const float*)d_in[6];
    float* out = (float*)d_out;

    // W2 transpose (for coalesced sparse row accumulation)
    transpose_kernel<<<dim3(H_ / 32, H_ / 32), dim3(32, 8)>>>(W2);

    // Time-parallel input GEMM (FFMA2)
    gemm1_kernel<<<dim3(H_ / 128, (B_ * T_) / 128), 256>>>(x, W1, b1);

    // Entire recurrence: one persistent per-batch kernel, no grid syncs
    batch_kernel<<<B_, 256>>>(Wout, b2, bout, out);
}